// round 3
// baseline (speedup 1.0000x reference)
#include <cuda_runtime.h>

// Problem constants
#define DD      512
#define TSEQ    512
#define NTOK    1024          // B*T = 2*512
#define NTHR    256
#define PER     (DD / NTHR)   // 2 d-elements per thread

// Per-token partial sums of res^2 (deterministic final reduce in kernel 2).
__device__ float g_partial[NTOK];

__device__ __forceinline__ float warpSum(float v) {
#pragma unroll
    for (int o = 16; o > 0; o >>= 1) v += __shfl_xor_sync(0xffffffffu, v, o);
    return v;  // butterfly: identical value in all lanes, deterministic
}

// Deterministic block-wide sum, broadcast to all threads.
__device__ __forceinline__ float blockSum(float v, float* red) {
    __syncthreads();  // protect red[] reuse across calls
    int lane = threadIdx.x & 31, w = threadIdx.x >> 5;
    v = warpSum(v);
    if (lane == 0) red[w] = v;
    __syncthreads();
    if (w == 0) {
        float x = (lane < (NTHR >> 5)) ? red[lane] : 0.0f;
        x = warpSum(x);
        if (lane == 0) red[0] = x;
    }
    __syncthreads();
    return red[0];
}

__global__ __launch_bounds__(NTHR) void token_kernel(
    const int*   __restrict__ token_ids,
    const float* __restrict__ resonances,
    const float* __restrict__ emb_scales,
    const float* __restrict__ emb_shifts,
    const float* __restrict__ emb_norm,
    const float* __restrict__ W_enc,   // [D,24]
    const float* __restrict__ b_enc,   // [24]
    const float* __restrict__ W_dec,   // [24,D]
    const float* __restrict__ b_dec,   // [D]
    const float* __restrict__ ecc_p,
    const float* __restrict__ ep_p,
    float*       __restrict__ out)     // [B,T,D] -> res (pre-fd)
{
    __shared__ float red[32];
    __shared__ float wpart[8][24];
    __shared__ float proj_s[24];
    __shared__ float corr_s[24];
    __shared__ float ein2_s;

    const int tid = threadIdx.x;
    const int tg  = blockIdx.x;            // token index b*T + t
    const int t   = tg & (TSEQ - 1);

    const float tv   = (float)(token_ids[tg] % 1000000) / 1000000.0f;
    const float base = tv + (float)t;
    const float embn = emb_norm[0];
    const float eccv = ecc_p[0];
    const float epv  = ep_p[0];

    // ---- embedding: comp = cos*(1+sin) + sin^2, scale/shift, token L2 norm ----
    float e0[PER];
    float ss = 0.0f;
#pragma unroll
    for (int i = 0; i < PER; i++) {
        int d = tid + i * NTHR;
        float ang = resonances[d] * base;
        float s, c;
        sincosf(ang, &s, &c);
        float comp = c * (1.0f + s) + s * s;
        float v = comp * emb_scales[d] + emb_shifts[d];
        e0[i] = v;
        ss += v * v;
    }
    float tn = sqrtf(blockSum(ss, red));

    float ss1 = 0.0f;
#pragma unroll
    for (int i = 0; i < PER; i++) {
        float v = (tn > 0.0f) ? (e0[i] * embn) / tn : e0[i];
        e0[i] = v;                 // normalized embedding, register-resident
        ss1 += v * v;
    }
    float e_in = sqrtf(blockSum(ss1, red));   // = ||emb|| after normalize

    // ---- proj = emb @ W_enc + b_enc  (512x24 matvec) ----
    float p[24];
#pragma unroll
    for (int l = 0; l < 24; l++) p[l] = 0.0f;
#pragma unroll
    for (int i = 0; i < PER; i++) {
        int d = tid + i * NTHR;
        float ev = e0[i];
        const float4* w4 = reinterpret_cast<const float4*>(W_enc + d * 24);
#pragma unroll
        for (int q = 0; q < 6; q++) {
            float4 w = w4[q];
            p[q * 4 + 0] += ev * w.x;
            p[q * 4 + 1] += ev * w.y;
            p[q * 4 + 2] += ev * w.z;
            p[q * 4 + 3] += ev * w.w;
        }
    }
#pragma unroll
    for (int l = 0; l < 24; l++) p[l] = warpSum(p[l]);
    {
        int lane = tid & 31, w = tid >> 5;
        if (lane < 24) wpart[w][lane] = p[lane];
    }
    __syncthreads();
    if (tid < 24) {
        float acc = b_enc[tid];
#pragma unroll
        for (int w = 0; w < 8; w++) acc += wpart[w][tid];
        proj_s[tid] = acc;
    }
    __syncthreads();

    // ---- Golay encode -> round to lattice -> rescale -> Golay decode -> threshold ----
    // GOLAY[k,l]: l<12: (l==k); 12<=l<23: (k+(l-12))%2; l==23: k%2
    if (tid == 0) {
        float pj[24];
#pragma unroll
        for (int l = 0; l < 24; l++) pj[l] = proj_s[l];
        float S_odd  = pj[13] + pj[15] + pj[17] + pj[19] + pj[21];
        float S_even = pj[12] + pj[14] + pj[16] + pj[18] + pj[20] + pj[22];

        float latt[12];
        float so = 0.0f;
#pragma unroll
        for (int k = 0; k < 12; k++) {
            float ge = pj[k] + ((k & 1) ? (S_even + pj[23]) : S_odd);
            float lr = rintf(ge / eccv) * eccv;   // round-half-even == jnp.round
            latt[k] = lr;
            so += lr * lr;
        }
        float e_out = sqrtf(so);
        float s1 = e_in / (e_out + 1e-8f);
        float so2 = 0.0f;
#pragma unroll
        for (int k = 0; k < 12; k++) {
            float v = (latt[k] * s1) * epv;
            latt[k] = v;
            so2 += v * v;
        }
        ein2_s = sqrtf(so2);                      // e_in2 = ||latt||

        float L_even = latt[0] + latt[2] + latt[4] + latt[6] + latt[8] + latt[10];
        float L_odd  = latt[1] + latt[3] + latt[5] + latt[7] + latt[9] + latt[11];
#pragma unroll
        for (int l = 0; l < 24; l++) {
            float v;
            if (l < 12)       v = latt[l];
            else if (l < 23)  v = (((l - 12) & 1) == 0) ? L_odd : L_even;
            else              v = L_odd;
            corr_s[l] = (fabsf(v) > eccv) ? v : 0.0f;   // "error correction"
        }
    }
    __syncthreads();

    // ---- res = corrected @ W_dec + b_dec, per-token energy rescale ----
    float rr[PER];
    float ss2 = 0.0f;
#pragma unroll
    for (int i = 0; i < PER; i++) {
        int d = tid + i * NTHR;
        float acc = b_dec[d];
#pragma unroll
        for (int l = 0; l < 24; l++) acc += corr_s[l] * W_dec[l * DD + d];
        rr[i] = acc;
        ss2 += acc * acc;
    }
    float ss2tot = blockSum(ss2, red);
    float e_out2 = sqrtf(ss2tot);
    float sc = ein2_s / (e_out2 + 1e-8f);

    float* orow = out + (size_t)tg * DD;
#pragma unroll
    for (int i = 0; i < PER; i++) {
        int d = tid + i * NTHR;
        orow[d] = (rr[i] * sc) * epv;
    }
    if (tid == 0) {
        float f = sc * epv;
        g_partial[tg] = f * f * ss2tot;   // Σ res^2 for this token
    }
}

// Final modulation: fd * frac_norm * ||res|| / |fd|  ==  frac_norm * ||res||
__global__ __launch_bounds__(NTHR) void scale_kernel(
    float* __restrict__ out, const float* __restrict__ frac_norm, int n4)
{
    __shared__ float red[32];
    __shared__ float fac_s;
    int tid = threadIdx.x;

    // Every block redoes the (cheap, L2-hit) deterministic reduce -> identical fac.
    float v = g_partial[tid] + g_partial[tid + 256] +
              g_partial[tid + 512] + g_partial[tid + 768];
    float tot = blockSum(v, red);
    if (tid == 0) fac_s = frac_norm[0] * sqrtf(tot);
    __syncthreads();
    float fac = fac_s;

    float4* o4 = reinterpret_cast<float4*>(out);
    for (int i = blockIdx.x * blockDim.x + tid; i < n4; i += gridDim.x * blockDim.x) {
        float4 x = o4[i];
        x.x *= fac; x.y *= fac; x.z *= fac; x.w *= fac;
        o4[i] = x;
    }
}

extern "C" void kernel_launch(void* const* d_in, const int* in_sizes, int n_in,
                              void* d_out, int out_size)
{
    const int*   token_ids  = (const int*)  d_in[0];
    const float* resonances = (const float*)d_in[1];
    const float* emb_scales = (const float*)d_in[2];
    const float* emb_shifts = (const float*)d_in[3];
    const float* emb_norm   = (const float*)d_in[4];
    // d_in[5] scale_weights, d_in[6] fractal_bias: algebraically dead (fd cancels)
    const float* frac_norm  = (const float*)d_in[7];
    const float* W_enc      = (const float*)d_in[8];
    const float* b_enc      = (const float*)d_in[9];
    const float* W_dec      = (const float*)d_in[10];
    const float* b_dec      = (const float*)d_in[11];
    const float* ecc        = (const float*)d_in[12];
    const float* ep         = (const float*)d_in[13];
    float* out = (float*)d_out;

    token_kernel<<<NTOK, NTHR>>>(token_ids, resonances, emb_scales, emb_shifts,
                                 emb_norm, W_enc, b_enc, W_dec, b_dec, ecc, ep, out);
    scale_kernel<<<256, NTHR>>>(out, frac_norm, out_size / 4);
}

// round 4
// speedup vs baseline: 1.8278x; 1.8278x over previous
#include <cuda_runtime.h>

#define DD      512
#define TSEQ    512
#define NTOK    1024          // B*T
#define NTHR    128           // threads per token block (4 warps)
#define PER     4             // d-elements per thread (float4 granularity)

__device__ float        g_partial[NTOK];
__device__ float        g_fac;
__device__ unsigned int g_cnt;   // zero-initialized; self-resetting per launch

__device__ __forceinline__ float warpSum(float v) {
#pragma unroll
    for (int o = 16; o > 0; o >>= 1) v += __shfl_xor_sync(0xffffffffu, v, o);
    return v;  // butterfly: same value in all lanes, deterministic
}

// Deterministic block-wide sum (4 warps), broadcast to all threads.
__device__ __forceinline__ float blockSum(float v, float* red) {
    __syncthreads();                       // protect red[] reuse
    int lane = threadIdx.x & 31, w = threadIdx.x >> 5;
    v = warpSum(v);
    if (lane == 0) red[w] = v;
    __syncthreads();
    return red[0] + red[1] + red[2] + red[3];   // fixed order, all threads
}

__global__ __launch_bounds__(NTHR) void token_kernel(
    const int*   __restrict__ token_ids,
    const float* __restrict__ resonances,
    const float* __restrict__ emb_scales,
    const float* __restrict__ emb_shifts,
    const float* __restrict__ emb_norm,
    const float* __restrict__ frac_norm,
    const float* __restrict__ W_enc,   // [D,24]
    const float* __restrict__ b_enc,   // [24]
    const float* __restrict__ W_dec,   // [24,D]
    const float* __restrict__ b_dec,   // [D]
    const float* __restrict__ ecc_p,
    const float* __restrict__ ep_p,
    float*       __restrict__ out)     // [B,T,D] -> res (pre-modulation)
{
    __shared__ float red[4];
    __shared__ float e0s[DD];
    __shared__ float proj_s[24];
    __shared__ float latt_s[12];
    __shared__ float corr_s[24];
    __shared__ float ein2_s;
    __shared__ int   done_s;

    const int tid  = threadIdx.x;
    const int lane = tid & 31;
    const int w    = tid >> 5;
    const int tg   = blockIdx.x;
    const int t    = tg & (TSEQ - 1);

    const float tv   = (float)(token_ids[tg] % 1000000) / 1000000.0f;
    const float base = tv + (float)t;
    const float embn = emb_norm[0];
    const float eccv = ecc_p[0];
    const float epv  = ep_p[0];

    // ---- embedding: comp = cos*(1+sin)+sin^2, scale/shift; d = 4*tid + i ----
    const float4 rs4 = ((const float4*)resonances)[tid];
    const float4 sc4 = ((const float4*)emb_scales)[tid];
    const float4 sh4 = ((const float4*)emb_shifts)[tid];
    const float rsv[4] = {rs4.x, rs4.y, rs4.z, rs4.w};
    const float scv[4] = {sc4.x, sc4.y, sc4.z, sc4.w};
    const float shv[4] = {sh4.x, sh4.y, sh4.z, sh4.w};

    float e0[PER];
    float ss = 0.0f;
#pragma unroll
    for (int i = 0; i < PER; i++) {
        float s, c;
        sincosf(rsv[i] * base, &s, &c);
        float v = (c * (1.0f + s) + s * s) * scv[i] + shv[i];
        e0[i] = v;
        ss += v * v;
    }
    float tn = sqrtf(blockSum(ss, red));
    // After normalize, ||emb|| == embn exactly (up to ~1e-7 rounding); skip 2nd reduce.
    float e_in = (tn > 0.0f) ? embn : 0.0f;

    float4 ev4;
#pragma unroll
    for (int i = 0; i < PER; i++) {
        float v = (tn > 0.0f) ? (e0[i] * embn) / tn : e0[i];
        ((float*)&ev4)[i] = v;
    }
    ((float4*)e0s)[tid] = ev4;
    __syncthreads();

    // ---- proj = emb @ W_enc + b_enc: warp w owns outputs [6w, 6w+6) ----
    {
        const int lbase = w * 6;
        float acc0=0.f, acc1=0.f, acc2=0.f, acc3=0.f, acc4=0.f, acc5=0.f;
#pragma unroll
        for (int j = 0; j < 16; j++) {
            int d = lane + 32 * j;
            float ev = e0s[d];
            const float2* w2 = (const float2*)(W_enc + d * 24 + lbase);
            float2 a = w2[0], b = w2[1], c = w2[2];
            acc0 += ev * a.x;  acc1 += ev * a.y;
            acc2 += ev * b.x;  acc3 += ev * b.y;
            acc4 += ev * c.x;  acc5 += ev * c.y;
        }
        acc0 = warpSum(acc0); acc1 = warpSum(acc1); acc2 = warpSum(acc2);
        acc3 = warpSum(acc3); acc4 = warpSum(acc4); acc5 = warpSum(acc5);
        if (lane == 0) {
            proj_s[lbase + 0] = acc0 + b_enc[lbase + 0];
            proj_s[lbase + 1] = acc1 + b_enc[lbase + 1];
            proj_s[lbase + 2] = acc2 + b_enc[lbase + 2];
            proj_s[lbase + 3] = acc3 + b_enc[lbase + 3];
            proj_s[lbase + 4] = acc4 + b_enc[lbase + 4];
            proj_s[lbase + 5] = acc5 + b_enc[lbase + 5];
        }
    }
    __syncthreads();

    // ---- Golay enc -> lattice round -> rescale -> Golay dec -> threshold ----
    // Parallelized over warp 0 lanes (12 IEEE divides run concurrently).
    if (w == 0) {
        float S_odd  = proj_s[13] + proj_s[15] + proj_s[17] + proj_s[19] + proj_s[21];
        float S_even = proj_s[12] + proj_s[14] + proj_s[16] + proj_s[18] + proj_s[20] + proj_s[22];
        float p23    = proj_s[23];

        float lr = 0.0f;
        if (lane < 12) {
            float ge = proj_s[lane] + ((lane & 1) ? (S_even + p23) : S_odd);
            lr = rintf(ge / eccv) * eccv;       // IEEE div: rintf boundary fidelity
        }
        float e_out = sqrtf(warpSum(lr * lr));
        float s1 = e_in / (e_out + 1e-8f);
        float lv = (lr * s1) * epv;
        float so2 = warpSum(lv * lv);
        if (lane == 0) ein2_s = sqrtf(so2);

        float L_even = warpSum((lane < 12 && !(lane & 1)) ? lv : 0.0f);
        float L_odd  = warpSum((lane < 12 &&  (lane & 1)) ? lv : 0.0f);
        if (lane < 12) latt_s[lane] = lv;
        __syncwarp();
        if (lane < 24) {
            float vv;
            if (lane < 12)      vv = latt_s[lane];
            else if (lane < 23) vv = (((lane - 12) & 1) == 0) ? L_odd : L_even;
            else                vv = L_odd;
            corr_s[lane] = (fabsf(vv) > eccv) ? vv : 0.0f;
        }
    }
    __syncthreads();

    // ---- res = corrected @ W_dec + b_dec (float4, fully coalesced) ----
    const float4 bd4 = ((const float4*)b_dec)[tid];
    float r0 = bd4.x, r1 = bd4.y, r2 = bd4.z, r3 = bd4.w;
#pragma unroll
    for (int l = 0; l < 24; l++) {
        float cl = corr_s[l];
        float4 wv = ((const float4*)(W_dec + l * DD))[tid];
        r0 += cl * wv.x;  r1 += cl * wv.y;
        r2 += cl * wv.z;  r3 += cl * wv.w;
    }
    float ss2 = r0*r0 + r1*r1 + r2*r2 + r3*r3;
    float ss2tot = blockSum(ss2, red);
    float sc = ein2_s / (sqrtf(ss2tot) + 1e-8f);

    float4 o4;
    o4.x = (r0 * sc) * epv;  o4.y = (r1 * sc) * epv;
    o4.z = (r2 * sc) * epv;  o4.w = (r3 * sc) * epv;
    ((float4*)out)[tg * (DD / 4) + tid] = o4;

    // ---- last-block global reduce of Σ res^2 -> g_fac (deterministic) ----
    if (tid == 0) {
        float f = sc * epv;
        g_partial[tg] = f * f * ss2tot;
        __threadfence();
        unsigned int old = atomicAdd(&g_cnt, 1u);
        done_s = (old == NTOK - 1) ? 1 : 0;
    }
    __syncthreads();
    if (done_s) {
        float v = 0.0f;
#pragma unroll
        for (int i = 0; i < NTOK / NTHR; i++) v += g_partial[tid + i * NTHR];
        float tot = blockSum(v, red);
        if (tid == 0) {
            g_fac = frac_norm[0] * sqrtf(tot);  // fd cancels: out = res*frac_norm*||res||
            g_cnt = 0u;                          // reset for next graph replay
        }
    }
}

// Pure streaming scale: one float4 per thread, scalar broadcast from g_fac.
__global__ __launch_bounds__(256) void scale_kernel(float4* __restrict__ out, int n4)
{
    int i = blockIdx.x * blockDim.x + threadIdx.x;
    float fac = g_fac;
    if (i < n4) {
        float4 x = out[i];
        x.x *= fac; x.y *= fac; x.z *= fac; x.w *= fac;
        out[i] = x;
    }
}

extern "C" void kernel_launch(void* const* d_in, const int* in_sizes, int n_in,
                              void* d_out, int out_size)
{
    const int*   token_ids  = (const int*)  d_in[0];
    const float* resonances = (const float*)d_in[1];
    const float* emb_scales = (const float*)d_in[2];
    const float* emb_shifts = (const float*)d_in[3];
    const float* emb_norm   = (const float*)d_in[4];
    // d_in[5] scale_weights, d_in[6] fractal_bias: dead (fd cancels in fd*||res||/|fd|)
    const float* frac_norm  = (const float*)d_in[7];
    const float* W_enc      = (const float*)d_in[8];
    const float* b_enc      = (const float*)d_in[9];
    const float* W_dec      = (const float*)d_in[10];
    const float* b_dec      = (const float*)d_in[11];
    const float* ecc        = (const float*)d_in[12];
    const float* ep         = (const float*)d_in[13];
    float* out = (float*)d_out;

    token_kernel<<<NTOK, NTHR>>>(token_ids, resonances, emb_scales, emb_shifts,
                                 emb_norm, frac_norm, W_enc, b_enc, W_dec, b_dec,
                                 ecc, ep, out);
    int n4 = out_size / 4;
    scale_kernel<<<(n4 + 255) / 256, 256>>>((float4*)out, n4);
}

// round 6
// speedup vs baseline: 1.8494x; 1.0118x over previous
#include <cuda_runtime.h>

#define DD      512
#define TSEQ    512
#define NTOK    1024          // B*T
#define NTHR    128           // threads per token block (4 warps)
#define PER     4             // d-elements per thread (float4 granularity)

__device__ float        g_partial[NTOK];
__device__ float        g_fac;
__device__ unsigned int g_cnt;    // arrival counter (self-resetting)
__device__ unsigned int g_cnt2;   // departure counter (self-resetting)
__device__ unsigned int g_flag;   // release flag     (self-resetting)

__device__ __forceinline__ float warpSum(float v) {
#pragma unroll
    for (int o = 16; o > 0; o >>= 1) v += __shfl_xor_sync(0xffffffffu, v, o);
    return v;  // butterfly: same value in all lanes, deterministic
}

// Deterministic block-wide sum (4 warps), broadcast to all threads.
__device__ __forceinline__ float blockSum(float v, float* red) {
    __syncthreads();                       // protect red[] reuse
    int lane = threadIdx.x & 31, w = threadIdx.x >> 5;
    v = warpSum(v);
    if (lane == 0) red[w] = v;
    __syncthreads();
    return red[0] + red[1] + red[2] + red[3];   // fixed order, all threads
}

__global__ __launch_bounds__(NTHR, 8) void fused_kernel(
    const int*   __restrict__ token_ids,
    const float* __restrict__ resonances,
    const float* __restrict__ emb_scales,
    const float* __restrict__ emb_shifts,
    const float* __restrict__ emb_norm,
    const float* __restrict__ frac_norm,
    const float* __restrict__ W_enc,   // [D,24]
    const float* __restrict__ b_enc,   // [24]
    const float* __restrict__ W_dec,   // [24,D]
    const float* __restrict__ b_dec,   // [D]
    const float* __restrict__ ecc_p,
    const float* __restrict__ ep_p,
    float*       __restrict__ out)     // [B,T,D]
{
    __shared__ float red[4];
    __shared__ float e0s[DD];
    __shared__ float proj_s[24];
    __shared__ float latt_s[12];
    __shared__ float corr_s[24];
    __shared__ float ein2_s;
    __shared__ float fac_s;
    __shared__ int   done_s;

    const int tid  = threadIdx.x;
    const int lane = tid & 31;
    const int w    = tid >> 5;
    const int tg   = blockIdx.x;
    const int t    = tg & (TSEQ - 1);

    const float tv   = (float)(token_ids[tg] % 1000000) / 1000000.0f;
    const float base = tv + (float)t;
    const float embn = emb_norm[0];
    const float eccv = ecc_p[0];
    const float epv  = ep_p[0];

    // ---- embedding: comp = cos*(1+sin)+sin^2, scale/shift; d = 4*tid + i ----
    const float4 rs4 = ((const float4*)resonances)[tid];
    const float4 sc4 = ((const float4*)emb_scales)[tid];
    const float4 sh4 = ((const float4*)emb_shifts)[tid];
    const float rsv[4] = {rs4.x, rs4.y, rs4.z, rs4.w};
    const float scv[4] = {sc4.x, sc4.y, sc4.z, sc4.w};
    const float shv[4] = {sh4.x, sh4.y, sh4.z, sh4.w};

    float e0[PER];
    float ss = 0.0f;
#pragma unroll
    for (int i = 0; i < PER; i++) {
        float s, c;
        sincosf(rsv[i] * base, &s, &c);
        float v = (c * (1.0f + s) + s * s) * scv[i] + shv[i];
        e0[i] = v;
        ss += v * v;
    }
    float tn = sqrtf(blockSum(ss, red));
    // After normalize, ||emb|| == embn up to ~1e-7 rounding; skip second reduce.
    float e_in = (tn > 0.0f) ? embn : 0.0f;

    float4 ev4;
#pragma unroll
    for (int i = 0; i < PER; i++) {
        float v = (tn > 0.0f) ? (e0[i] * embn) / tn : e0[i];
        ((float*)&ev4)[i] = v;
    }
    ((float4*)e0s)[tid] = ev4;
    __syncthreads();

    // ---- proj = emb @ W_enc + b_enc: warp w owns outputs [6w, 6w+6) ----
    {
        const int lbase = w * 6;
        float acc0=0.f, acc1=0.f, acc2=0.f, acc3=0.f, acc4=0.f, acc5=0.f;
#pragma unroll
        for (int j = 0; j < 16; j++) {
            int d = lane + 32 * j;
            float ev = e0s[d];
            const float2* w2 = (const float2*)(W_enc + d * 24 + lbase);
            float2 a = w2[0], b = w2[1], c = w2[2];
            acc0 += ev * a.x;  acc1 += ev * a.y;
            acc2 += ev * b.x;  acc3 += ev * b.y;
            acc4 += ev * c.x;  acc5 += ev * c.y;
        }
        acc0 = warpSum(acc0); acc1 = warpSum(acc1); acc2 = warpSum(acc2);
        acc3 = warpSum(acc3); acc4 = warpSum(acc4); acc5 = warpSum(acc5);
        if (lane == 0) {
            proj_s[lbase + 0] = acc0 + b_enc[lbase + 0];
            proj_s[lbase + 1] = acc1 + b_enc[lbase + 1];
            proj_s[lbase + 2] = acc2 + b_enc[lbase + 2];
            proj_s[lbase + 3] = acc3 + b_enc[lbase + 3];
            proj_s[lbase + 4] = acc4 + b_enc[lbase + 4];
            proj_s[lbase + 5] = acc5 + b_enc[lbase + 5];
        }
    }
    __syncthreads();

    // ---- Golay enc -> lattice round -> rescale -> Golay dec -> threshold ----
    if (w == 0) {
        float S_odd  = proj_s[13] + proj_s[15] + proj_s[17] + proj_s[19] + proj_s[21];
        float S_even = proj_s[12] + proj_s[14] + proj_s[16] + proj_s[18] + proj_s[20] + proj_s[22];
        float p23    = proj_s[23];

        float lr = 0.0f;
        if (lane < 12) {
            float ge = proj_s[lane] + ((lane & 1) ? (S_even + p23) : S_odd);
            lr = rintf(ge / eccv) * eccv;       // IEEE div: rintf boundary fidelity
        }
        float e_out = sqrtf(warpSum(lr * lr));
        float s1 = e_in / (e_out + 1e-8f);
        float lv = (lr * s1) * epv;
        float so2 = warpSum(lv * lv);
        if (lane == 0) ein2_s = sqrtf(so2);

        float L_even = warpSum((lane < 12 && !(lane & 1)) ? lv : 0.0f);
        float L_odd  = warpSum((lane < 12 &&  (lane & 1)) ? lv : 0.0f);
        if (lane < 12) latt_s[lane] = lv;
        __syncwarp();
        if (lane < 24) {
            float vv;
            if (lane < 12)      vv = latt_s[lane];
            else if (lane < 23) vv = (((lane - 12) & 1) == 0) ? L_odd : L_even;
            else                vv = L_odd;
            corr_s[lane] = (fabsf(vv) > eccv) ? vv : 0.0f;
        }
    }
    __syncthreads();

    // ---- res = corrected @ W_dec + b_dec (float4, fully coalesced) ----
    const float4 bd4 = ((const float4*)b_dec)[tid];
    float r0 = bd4.x, r1 = bd4.y, r2 = bd4.z, r3 = bd4.w;
#pragma unroll
    for (int l = 0; l < 24; l++) {
        float cl = corr_s[l];
        float4 wv = ((const float4*)(W_dec + l * DD))[tid];
        r0 += cl * wv.x;  r1 += cl * wv.y;
        r2 += cl * wv.z;  r3 += cl * wv.w;
    }
    float ss2 = r0*r0 + r1*r1 + r2*r2 + r3*r3;
    float ss2tot = blockSum(ss2, red);
    float sc = ein2_s / (sqrtf(ss2tot) + 1e-8f);
    float fpre = sc * epv;                 // per-token rescale (res stays in regs)

    // ---- grid-wide barrier: publish Sigma res^2, last block reduces -> g_fac ----
    if (tid == 0) {
        g_partial[tg] = fpre * fpre * ss2tot;
        __threadfence();
        unsigned int old = atomicAdd(&g_cnt, 1u);
        done_s = (old == NTOK - 1) ? 1 : 0;
    }
    __syncthreads();
    if (done_s) {
        float v = 0.0f;
#pragma unroll
        for (int i = 0; i < NTOK / NTHR; i++) v += g_partial[tid + i * NTHR];
        float tot = blockSum(v, red);
        if (tid == 0) {
            // fd cancels: out = res * frac_norm * ||res||
            *(volatile float*)&g_fac = frac_norm[0] * sqrtf(tot);
            __threadfence();
            atomicExch(&g_flag, 1u);
        }
    }
    if (tid == 0) {
        while (*(volatile unsigned int*)&g_flag == 0u) __nanosleep(64);
        fac_s = *(volatile float*)&g_fac;   // volatile: bypass (incoherent) L1
    }
    __syncthreads();
    const float fac = fac_s * fpre;

    // ---- single output write, fully scaled ----
    float4 o4;
    o4.x = r0 * fac;  o4.y = r1 * fac;
    o4.z = r2 * fac;  o4.w = r3 * fac;
    ((float4*)out)[tg * (DD / 4) + tid] = o4;

    // ---- self-reset for graph replay (after all blocks passed the spin) ----
    if (tid == 0) {
        unsigned int old2 = atomicAdd(&g_cnt2, 1u);
        if (old2 == NTOK - 1) {
            g_flag = 0u;
            g_cnt  = 0u;
            g_cnt2 = 0u;
        }
    }
}

extern "C" void kernel_launch(void* const* d_in, const int* in_sizes, int n_in,
                              void* d_out, int out_size)
{
    const int*   token_ids  = (const int*)  d_in[0];
    const float* resonances = (const float*)d_in[1];
    const float* emb_scales = (const float*)d_in[2];
    const float* emb_shifts = (const float*)d_in[3];
    const float* emb_norm   = (const float*)d_in[4];
    // d_in[5] scale_weights, d_in[6] fractal_bias: dead (fd cancels in fd*||res||/|fd|)
    const float* frac_norm  = (const float*)d_in[7];
    const float* W_enc      = (const float*)d_in[8];
    const float* b_enc      = (const float*)d_in[9];
    const float* W_dec      = (const float*)d_in[10];
    const float* b_dec      = (const float*)d_in[11];
    const float* ecc        = (const float*)d_in[12];
    const float* ep         = (const float*)d_in[13];
    float* out = (float*)d_out;

    fused_kernel<<<NTOK, NTHR>>>(token_ids, resonances, emb_scales, emb_shifts,
                                 emb_norm, frac_norm, W_enc, b_enc, W_dec, b_dec,
                                 ecc, ep, out);
}